// round 1
// baseline (speedup 1.0000x reference)
#include <cuda_runtime.h>
#include <cuda_bf16.h>

#define FDIM 128

// Vector reduction (no return value) into global memory. sm_90+.
__device__ __forceinline__ void red_add_v4(float* addr, float4 v) {
    asm volatile("red.global.add.v4.f32 [%0], {%1, %2, %3, %4};"
                 :: "l"(addr), "f"(v.x), "f"(v.y), "f"(v.z), "f"(v.w)
                 : "memory");
}

// One warp processes CHUNK consecutive rows. Lane l owns features [4l, 4l+4).
// Segment ids are sorted, so we accumulate in registers and flush to global
// (vector red) only on segment change / chunk end.
template <int CHUNK, bool WRITE_LOGITS>
__global__ void gated_segsum_kernel(const float* __restrict__ feats,
                                    const float* __restrict__ W,
                                    const float* __restrict__ bptr,
                                    const int*   __restrict__ seg,
                                    int n_rows,
                                    float* __restrict__ out_sum,
                                    float* __restrict__ out_logits)
{
    const int warp = (int)((blockIdx.x * blockDim.x + threadIdx.x) >> 5);
    const int lane = threadIdx.x & 31;

    long row0 = (long)warp * CHUNK;
    if (row0 >= n_rows) return;
    const long row_end = min((long)n_rows, row0 + CHUNK);

    // Gate weights: 128 floats, 4 per lane. Bias scalar.
    const float4 w4  = *reinterpret_cast<const float4*>(W + lane * 4);
    const float bias = __ldg(bptr);

    float4 acc = make_float4(0.f, 0.f, 0.f, 0.f);
    int cur = __ldg(seg + row0);

    for (long r = row0; r < row_end; ++r) {
        const float4 f = *reinterpret_cast<const float4*>(feats + r * FDIM + lane * 4);

        // 128-dot: per-lane partial then butterfly reduce (all lanes get result)
        float p = f.x * w4.x + f.y * w4.y + f.z * w4.z + f.w * w4.w;
        #pragma unroll
        for (int o = 16; o > 0; o >>= 1)
            p += __shfl_xor_sync(0xffffffffu, p, o);

        const float logit = p + bias;
        if (WRITE_LOGITS) {
            if (lane == 0) out_logits[r] = logit;
        }
        const float g = 1.0f / (1.0f + __expf(-logit));

        const int s = __ldg(seg + r);   // uniform per warp, L1-resident
        if (s != cur) {
            red_add_v4(out_sum + (long)cur * FDIM + lane * 4, acc);
            acc = make_float4(0.f, 0.f, 0.f, 0.f);
            cur = s;
        }
        acc.x += g * f.x;
        acc.y += g * f.y;
        acc.z += g * f.z;
        acc.w += g * f.w;
    }
    red_add_v4(out_sum + (long)cur * FDIM + lane * 4, acc);
}

extern "C" void kernel_launch(void* const* d_in, const int* in_sizes, int n_in,
                              void* d_out, int out_size) {
    const float* atom_feats = (const float*)d_in[0];
    const float* vir_feats  = (const float*)d_in[1];
    const float* W_atom     = (const float*)d_in[2];
    const float* b_atom     = (const float*)d_in[3];
    const float* W_vir      = (const float*)d_in[4];
    const float* b_vir      = (const float*)d_in[5];
    const int*   atom_seg   = (const int*)d_in[6];
    const int*   vir_seg    = (const int*)d_in[7];

    const int n_atom = in_sizes[0] / FDIM;
    const int n_vir  = in_sizes[1] / FDIM;
    // out layout: [num_graphs*128 atom sums][num_graphs*128 vir sums][n_atom logits]
    const int num_graphs = (out_size - n_atom) / (2 * FDIM);

    float* out       = (float*)d_out;
    float* sum_atom  = out;
    float* sum_vir   = out + (size_t)num_graphs * FDIM;
    float* logits    = out + (size_t)num_graphs * FDIM * 2;

    // Zero only the segment-sum regions (logits fully overwritten).
    cudaMemsetAsync(out, 0, (size_t)num_graphs * FDIM * 2 * sizeof(float), 0);

    constexpr int CHUNK_A = 64;   // ~50 rows/segment -> ~2 flushes per chunk
    constexpr int CHUNK_V = 8;    // ~4 rows/segment
    constexpr int THREADS = 256;  // 8 warps / CTA

    {
        int chunks = (n_atom + CHUNK_A - 1) / CHUNK_A;
        int blocks = (chunks + 7) / 8;
        gated_segsum_kernel<CHUNK_A, true><<<blocks, THREADS>>>(
            atom_feats, W_atom, b_atom, atom_seg, n_atom, sum_atom, logits);
    }
    {
        int chunks = (n_vir + CHUNK_V - 1) / CHUNK_V;
        int blocks = (chunks + 7) / 8;
        gated_segsum_kernel<CHUNK_V, false><<<blocks, THREADS>>>(
            vir_feats, W_vir, b_vir, vir_seg, n_vir, sum_vir, nullptr);
    }
}

// round 3
// speedup vs baseline: 1.7262x; 1.7262x over previous
#include <cuda_runtime.h>
#include <cuda_bf16.h>

#define FDIM 128

// Vector reduction (no return) into global memory.
__device__ __forceinline__ void red_add_v4(float* addr, float4 v) {
    asm volatile("red.global.add.v4.f32 [%0], {%1, %2, %3, %4};"
                 :: "l"(addr), "f"(v.x), "f"(v.y), "f"(v.z), "f"(v.w)
                 : "memory");
}

__device__ __forceinline__ float sigmoidf_fast(float x) {
    return 1.0f / (1.0f + __expf(-x));
}

// One warp processes CHUNK consecutive rows, unrolled by 4 for MLP/ILP.
// Lane l owns features [4l, 4l+4). Sorted segments -> register accumulate,
// flush via red.global only at segment boundaries.
template <int CHUNK, bool WRITE_LOGITS>
__device__ __forceinline__ void run_side(const float* __restrict__ feats,
                                         const float* __restrict__ W,
                                         const float* __restrict__ bptr,
                                         const int*   __restrict__ seg,
                                         int n_rows,
                                         float* __restrict__ out_sum,
                                         float* __restrict__ out_logits,
                                         int chunk_idx, int lane)
{
    long row0 = (long)chunk_idx * CHUNK;
    if (row0 >= n_rows) return;
    const long row_end = min((long)n_rows, row0 + CHUNK);

    const float4 w4  = *reinterpret_cast<const float4*>(W + lane * 4);
    const float bias = __ldg(bptr);

    float4 acc = make_float4(0.f, 0.f, 0.f, 0.f);
    int cur = __ldg(seg + row0);

    long r = row0;
    // Unrolled-by-4 main body: 4 independent load+reduce chains in flight.
    for (; r + 3 < row_end; r += 4) {
        const float4 f0 = *reinterpret_cast<const float4*>(feats + (r + 0) * FDIM + lane * 4);
        const float4 f1 = *reinterpret_cast<const float4*>(feats + (r + 1) * FDIM + lane * 4);
        const float4 f2 = *reinterpret_cast<const float4*>(feats + (r + 2) * FDIM + lane * 4);
        const float4 f3 = *reinterpret_cast<const float4*>(feats + (r + 3) * FDIM + lane * 4);
        const int4  s4  = *reinterpret_cast<const int4*>(seg + r);   // uniform, L1-hit

        float p0 = f0.x * w4.x + f0.y * w4.y + f0.z * w4.z + f0.w * w4.w;
        float p1 = f1.x * w4.x + f1.y * w4.y + f1.z * w4.z + f1.w * w4.w;
        float p2 = f2.x * w4.x + f2.y * w4.y + f2.z * w4.z + f2.w * w4.w;
        float p3 = f3.x * w4.x + f3.y * w4.y + f3.z * w4.z + f3.w * w4.w;

        // 4 interleaved butterfly chains: SHFL latencies overlap across rows.
        #pragma unroll
        for (int o = 16; o > 0; o >>= 1) {
            p0 += __shfl_xor_sync(0xffffffffu, p0, o);
            p1 += __shfl_xor_sync(0xffffffffu, p1, o);
            p2 += __shfl_xor_sync(0xffffffffu, p2, o);
            p3 += __shfl_xor_sync(0xffffffffu, p3, o);
        }

        const float l0 = p0 + bias, l1 = p1 + bias, l2 = p2 + bias, l3 = p3 + bias;
        if (WRITE_LOGITS && lane == 0) {
            out_logits[r + 0] = l0;
            out_logits[r + 1] = l1;
            out_logits[r + 2] = l2;
            out_logits[r + 3] = l3;
        }
        const float g0 = sigmoidf_fast(l0);
        const float g1 = sigmoidf_fast(l1);
        const float g2 = sigmoidf_fast(l2);
        const float g3 = sigmoidf_fast(l3);

        // Per-row segment-boundary handling (rare on atom side).
        if (s4.x != cur) { red_add_v4(out_sum + (long)cur * FDIM + lane * 4, acc);
                           acc = make_float4(0.f,0.f,0.f,0.f); cur = s4.x; }
        acc.x += g0 * f0.x; acc.y += g0 * f0.y; acc.z += g0 * f0.z; acc.w += g0 * f0.w;

        if (s4.y != cur) { red_add_v4(out_sum + (long)cur * FDIM + lane * 4, acc);
                           acc = make_float4(0.f,0.f,0.f,0.f); cur = s4.y; }
        acc.x += g1 * f1.x; acc.y += g1 * f1.y; acc.z += g1 * f1.z; acc.w += g1 * f1.w;

        if (s4.z != cur) { red_add_v4(out_sum + (long)cur * FDIM + lane * 4, acc);
                           acc = make_float4(0.f,0.f,0.f,0.f); cur = s4.z; }
        acc.x += g2 * f2.x; acc.y += g2 * f2.y; acc.z += g2 * f2.z; acc.w += g2 * f2.w;

        if (s4.w != cur) { red_add_v4(out_sum + (long)cur * FDIM + lane * 4, acc);
                           acc = make_float4(0.f,0.f,0.f,0.f); cur = s4.w; }
        acc.x += g3 * f3.x; acc.y += g3 * f3.y; acc.z += g3 * f3.z; acc.w += g3 * f3.w;
    }
    // Scalar tail (not hit for the given shapes, kept for safety).
    for (; r < row_end; ++r) {
        const float4 f = *reinterpret_cast<const float4*>(feats + r * FDIM + lane * 4);
        float p = f.x * w4.x + f.y * w4.y + f.z * w4.z + f.w * w4.w;
        #pragma unroll
        for (int o = 16; o > 0; o >>= 1)
            p += __shfl_xor_sync(0xffffffffu, p, o);
        const float lg = p + bias;
        if (WRITE_LOGITS && lane == 0) out_logits[r] = lg;
        const float g = sigmoidf_fast(lg);
        const int s = __ldg(seg + r);
        if (s != cur) { red_add_v4(out_sum + (long)cur * FDIM + lane * 4, acc);
                        acc = make_float4(0.f,0.f,0.f,0.f); cur = s; }
        acc.x += g * f.x; acc.y += g * f.y; acc.z += g * f.z; acc.w += g * f.w;
    }
    red_add_v4(out_sum + (long)cur * FDIM + lane * 4, acc);
}

// Single fused launch: warps [0, atomChunks) do the atom side (CHUNK=64, logits),
// warps [atomChunks, atomChunks+virChunks) do the vir side (CHUNK=8).
__global__ __launch_bounds__(256)
void fused_gated_segsum(const float* __restrict__ atom_feats,
                        const float* __restrict__ W_atom,
                        const float* __restrict__ b_atom,
                        const int*   __restrict__ atom_seg,
                        int n_atom, int atom_chunks,
                        const float* __restrict__ vir_feats,
                        const float* __restrict__ W_vir,
                        const float* __restrict__ b_vir,
                        const int*   __restrict__ vir_seg,
                        int n_vir, int vir_chunks,
                        float* __restrict__ sum_atom,
                        float* __restrict__ sum_vir,
                        float* __restrict__ logits)
{
    const int warp = (int)((blockIdx.x * blockDim.x + threadIdx.x) >> 5);
    const int lane = threadIdx.x & 31;

    if (warp < atom_chunks) {
        run_side<64, true>(atom_feats, W_atom, b_atom, atom_seg, n_atom,
                           sum_atom, logits, warp, lane);
    } else if (warp < atom_chunks + vir_chunks) {
        run_side<8, false>(vir_feats, W_vir, b_vir, vir_seg, n_vir,
                           sum_vir, nullptr, warp - atom_chunks, lane);
    }
}

extern "C" void kernel_launch(void* const* d_in, const int* in_sizes, int n_in,
                              void* d_out, int out_size) {
    const float* atom_feats = (const float*)d_in[0];
    const float* vir_feats  = (const float*)d_in[1];
    const float* W_atom     = (const float*)d_in[2];
    const float* b_atom     = (const float*)d_in[3];
    const float* W_vir      = (const float*)d_in[4];
    const float* b_vir      = (const float*)d_in[5];
    const int*   atom_seg   = (const int*)d_in[6];
    const int*   vir_seg    = (const int*)d_in[7];

    const int n_atom = in_sizes[0] / FDIM;
    const int n_vir  = in_sizes[1] / FDIM;
    const int num_graphs = (out_size - n_atom) / (2 * FDIM);

    float* out      = (float*)d_out;
    float* sum_atom = out;
    float* sum_vir  = out + (size_t)num_graphs * FDIM;
    float* logits   = out + (size_t)num_graphs * FDIM * 2;

    // Zero only the segment-sum regions (logits fully overwritten).
    cudaMemsetAsync(out, 0, (size_t)num_graphs * FDIM * 2 * sizeof(float), 0);

    constexpr int CHUNK_A = 64;
    constexpr int CHUNK_V = 8;
    constexpr int THREADS = 256;   // 8 warps / CTA

    const int atom_chunks = (n_atom + CHUNK_A - 1) / CHUNK_A;
    const int vir_chunks  = (n_vir  + CHUNK_V - 1) / CHUNK_V;
    const int total_warps = atom_chunks + vir_chunks;
    const int blocks = (total_warps + 7) / 8;

    fused_gated_segsum<<<blocks, THREADS>>>(
        atom_feats, W_atom, b_atom, atom_seg, n_atom, atom_chunks,
        vir_feats,  W_vir,  b_vir,  vir_seg,  n_vir,  vir_chunks,
        sum_atom, sum_vir, logits);
}

// round 4
// speedup vs baseline: 1.7522x; 1.0151x over previous
#include <cuda_runtime.h>
#include <cuda_bf16.h>

#define FDIM 128

// Vector reduction (no return) into global memory.
__device__ __forceinline__ void red_add_v4(float* addr, float4 v) {
    asm volatile("red.global.add.v4.f32 [%0], {%1, %2, %3, %4};"
                 :: "l"(addr), "f"(v.x), "f"(v.y), "f"(v.z), "f"(v.w)
                 : "memory");
}

__device__ __forceinline__ float sigmoidf_fast(float x) {
    return 1.0f / (1.0f + __expf(-x));
}

// One warp processes CHUNK consecutive rows, unrolled by 8 for MLP.
// Lane l owns features [4l, 4l+4). Sorted segments -> register accumulate,
// flush via red.global only at segment boundaries. Group fast path when all
// 8 rows stay in the current segment (seg sorted: seg[r+7]==cur => all == cur).
template <int CHUNK, bool WRITE_LOGITS>
__device__ __forceinline__ void run_side(const float* __restrict__ feats,
                                         const float* __restrict__ W,
                                         const float* __restrict__ bptr,
                                         const int*   __restrict__ seg,
                                         int n_rows,
                                         float* __restrict__ out_sum,
                                         float* __restrict__ out_logits,
                                         int chunk_idx, int lane)
{
    long row0 = (long)chunk_idx * CHUNK;
    if (row0 >= n_rows) return;
    const long row_end = min((long)n_rows, row0 + CHUNK);

    const float4 w4  = *reinterpret_cast<const float4*>(W + lane * 4);
    const float bias = __ldg(bptr);

    float4 acc = make_float4(0.f, 0.f, 0.f, 0.f);
    int cur = __ldg(seg + row0);

    long r = row0;
    for (; r + 7 < row_end; r += 8) {
        // 8 independent LDG.128 issued up front.
        float4 f[8];
        #pragma unroll
        for (int i = 0; i < 8; ++i)
            f[i] = *reinterpret_cast<const float4*>(feats + (r + i) * FDIM + lane * 4);
        const int4 sa = *reinterpret_cast<const int4*>(seg + r);     // uniform, L1-hit
        const int4 sb = *reinterpret_cast<const int4*>(seg + r + 4);
        int s[8] = {sa.x, sa.y, sa.z, sa.w, sb.x, sb.y, sb.z, sb.w};

        float p[8];
        #pragma unroll
        for (int i = 0; i < 8; ++i)
            p[i] = f[i].x * w4.x + f[i].y * w4.y + f[i].z * w4.z + f[i].w * w4.w;

        // 8 interleaved butterfly chains: SHFL latencies overlap.
        #pragma unroll
        for (int o = 16; o > 0; o >>= 1) {
            #pragma unroll
            for (int i = 0; i < 8; ++i)
                p[i] += __shfl_xor_sync(0xffffffffu, p[i], o);
        }

        float g[8];
        #pragma unroll
        for (int i = 0; i < 8; ++i) {
            p[i] += bias;                 // logit
            g[i] = sigmoidf_fast(p[i]);
        }

        if (WRITE_LOGITS && lane == 0) {
            // r is a multiple of 8 -> 16B-aligned vector stores.
            *reinterpret_cast<float4*>(out_logits + r)     = make_float4(p[0], p[1], p[2], p[3]);
            *reinterpret_cast<float4*>(out_logits + r + 4) = make_float4(p[4], p[5], p[6], p[7]);
        }

        if (s[7] == cur) {
            // Fast path: whole group in current segment (sorted + s[i] >= cur).
            #pragma unroll
            for (int i = 0; i < 8; ++i) {
                acc.x += g[i] * f[i].x; acc.y += g[i] * f[i].y;
                acc.z += g[i] * f[i].z; acc.w += g[i] * f[i].w;
            }
        } else {
            #pragma unroll
            for (int i = 0; i < 8; ++i) {
                if (s[i] != cur) {
                    red_add_v4(out_sum + (long)cur * FDIM + lane * 4, acc);
                    acc = make_float4(0.f, 0.f, 0.f, 0.f);
                    cur = s[i];
                }
                acc.x += g[i] * f[i].x; acc.y += g[i] * f[i].y;
                acc.z += g[i] * f[i].z; acc.w += g[i] * f[i].w;
            }
        }
    }
    // Scalar tail (not hit for the given shapes, kept for safety).
    for (; r < row_end; ++r) {
        const float4 fv = *reinterpret_cast<const float4*>(feats + r * FDIM + lane * 4);
        float p = fv.x * w4.x + fv.y * w4.y + fv.z * w4.z + fv.w * w4.w;
        #pragma unroll
        for (int o = 16; o > 0; o >>= 1)
            p += __shfl_xor_sync(0xffffffffu, p, o);
        const float lg = p + bias;
        if (WRITE_LOGITS && lane == 0) out_logits[r] = lg;
        const float gv = sigmoidf_fast(lg);
        const int sv = __ldg(seg + r);
        if (sv != cur) {
            red_add_v4(out_sum + (long)cur * FDIM + lane * 4, acc);
            acc = make_float4(0.f, 0.f, 0.f, 0.f);
            cur = sv;
        }
        acc.x += gv * fv.x; acc.y += gv * fv.y; acc.z += gv * fv.z; acc.w += gv * fv.w;
    }
    red_add_v4(out_sum + (long)cur * FDIM + lane * 4, acc);
}

// Single fused launch: warps [0, atomChunks) do the atom side (CHUNK=64, logits),
// warps [atomChunks, atomChunks+virChunks) do the vir side (CHUNK=8).
__global__ __launch_bounds__(256, 3)
void fused_gated_segsum(const float* __restrict__ atom_feats,
                        const float* __restrict__ W_atom,
                        const float* __restrict__ b_atom,
                        const int*   __restrict__ atom_seg,
                        int n_atom, int atom_chunks,
                        const float* __restrict__ vir_feats,
                        const float* __restrict__ W_vir,
                        const float* __restrict__ b_vir,
                        const int*   __restrict__ vir_seg,
                        int n_vir, int vir_chunks,
                        float* __restrict__ sum_atom,
                        float* __restrict__ sum_vir,
                        float* __restrict__ logits)
{
    const int warp = (int)((blockIdx.x * blockDim.x + threadIdx.x) >> 5);
    const int lane = threadIdx.x & 31;

    if (warp < atom_chunks) {
        run_side<64, true>(atom_feats, W_atom, b_atom, atom_seg, n_atom,
                           sum_atom, logits, warp, lane);
    } else if (warp < atom_chunks + vir_chunks) {
        run_side<8, false>(vir_feats, W_vir, b_vir, vir_seg, n_vir,
                           sum_vir, nullptr, warp - atom_chunks, lane);
    }
}

extern "C" void kernel_launch(void* const* d_in, const int* in_sizes, int n_in,
                              void* d_out, int out_size) {
    const float* atom_feats = (const float*)d_in[0];
    const float* vir_feats  = (const float*)d_in[1];
    const float* W_atom     = (const float*)d_in[2];
    const float* b_atom     = (const float*)d_in[3];
    const float* W_vir      = (const float*)d_in[4];
    const float* b_vir      = (const float*)d_in[5];
    const int*   atom_seg   = (const int*)d_in[6];
    const int*   vir_seg    = (const int*)d_in[7];

    const int n_atom = in_sizes[0] / FDIM;
    const int n_vir  = in_sizes[1] / FDIM;
    const int num_graphs = (out_size - n_atom) / (2 * FDIM);

    float* out      = (float*)d_out;
    float* sum_atom = out;
    float* sum_vir  = out + (size_t)num_graphs * FDIM;
    float* logits   = out + (size_t)num_graphs * FDIM * 2;

    // Zero only the segment-sum regions (logits fully overwritten).
    cudaMemsetAsync(out, 0, (size_t)num_graphs * FDIM * 2 * sizeof(float), 0);

    constexpr int CHUNK_A = 64;
    constexpr int CHUNK_V = 8;
    constexpr int THREADS = 256;   // 8 warps / CTA

    const int atom_chunks = (n_atom + CHUNK_A - 1) / CHUNK_A;
    const int vir_chunks  = (n_vir  + CHUNK_V - 1) / CHUNK_V;
    const int total_warps = atom_chunks + vir_chunks;
    const int blocks = (total_warps + 7) / 8;

    fused_gated_segsum<<<blocks, THREADS>>>(
        atom_feats, W_atom, b_atom, atom_seg, n_atom, atom_chunks,
        vir_feats,  W_vir,  b_vir,  vir_seg,  n_vir,  vir_chunks,
        sum_atom, sum_vir, logits);
}